// round 1
// baseline (speedup 1.0000x reference)
#include <cuda_runtime.h>

#define NQ 8192
#define NKV 8192
#define DD 512

static constexpr float QSCALE = 0.044194173824159216f; // 1/sqrt(512)

// Scratch for projected q, k, v (16 MB each) — __device__ globals, no allocation.
__device__ float g_q[NQ * DD];
__device__ float g_k[NKV * DD];
__device__ float g_v[NKV * DD];

// ---------------------------------------------------------------------------
// Projection: O[row, col] = sum_d A[row, d] * W[col, d] + b[col]   (y = A W^T + b)
// 128x128 tile, BK=16, 256 threads, 8x8 per thread. gridDim.z selects q/k/v.
// 1/sqrt(D) folded into the q projection output.
// ---------------------------------------------------------------------------
__global__ __launch_bounds__(256) void proj_kernel(
    const float* __restrict__ x, const float* __restrict__ dom,
    const float* __restrict__ Wq, const float* __restrict__ bq,
    const float* __restrict__ Wk, const float* __restrict__ bk,
    const float* __restrict__ Wv, const float* __restrict__ bv)
{
    __shared__ float As[16][132];
    __shared__ float Bs[16][132];

    const int z = blockIdx.z;
    const float* A = (z == 0) ? x : dom;
    const float* W = (z == 0) ? Wq : (z == 1 ? Wk : Wv);
    const float* b = (z == 0) ? bq : (z == 1 ? bk : bv);
    float* O       = (z == 0) ? g_q : (z == 1 ? g_k : g_v);
    const float scale = (z == 0) ? QSCALE : 1.0f;

    const int tid = threadIdx.x;
    const int tx = tid & 15, ty = tid >> 4;
    const int rowBase = blockIdx.y * 128;
    const int colBase = blockIdx.x * 128;

    float acc[8][8];
#pragma unroll
    for (int i = 0; i < 8; ++i)
#pragma unroll
        for (int j = 0; j < 8; ++j) acc[i][j] = 0.0f;

    for (int kt = 0; kt < DD / 16; ++kt) {
        const int k0 = kt * 16;
#pragma unroll
        for (int it = 0; it < 2; ++it) {
            int idx = tid + 256 * it;          // 0..511 (128 rows x 4 float4)
            int r = idx >> 2, c4 = idx & 3;
            float4 a = *(const float4*)&A[(size_t)(rowBase + r) * DD + k0 + c4 * 4];
            As[c4 * 4 + 0][r] = a.x; As[c4 * 4 + 1][r] = a.y;
            As[c4 * 4 + 2][r] = a.z; As[c4 * 4 + 3][r] = a.w;
            float4 w = *(const float4*)&W[(size_t)(colBase + r) * DD + k0 + c4 * 4];
            Bs[c4 * 4 + 0][r] = w.x; Bs[c4 * 4 + 1][r] = w.y;
            Bs[c4 * 4 + 2][r] = w.z; Bs[c4 * 4 + 3][r] = w.w;
        }
        __syncthreads();
#pragma unroll
        for (int k = 0; k < 16; ++k) {
            float ar[8], br[8];
            *(float4*)&ar[0] = *(const float4*)&As[k][ty * 8];
            *(float4*)&ar[4] = *(const float4*)&As[k][ty * 8 + 4];
            *(float4*)&br[0] = *(const float4*)&Bs[k][tx * 8];
            *(float4*)&br[4] = *(const float4*)&Bs[k][tx * 8 + 4];
#pragma unroll
            for (int i = 0; i < 8; ++i)
#pragma unroll
                for (int j = 0; j < 8; ++j) acc[i][j] += ar[i] * br[j];
        }
        __syncthreads();
    }

#pragma unroll
    for (int i = 0; i < 8; ++i) {
        int row = rowBase + ty * 8 + i;
#pragma unroll
        for (int jj = 0; jj < 2; ++jj) {
            int col = colBase + tx * 8 + jj * 4;
            float4 r4;
            r4.x = (acc[i][jj * 4 + 0] + b[col + 0]) * scale;
            r4.y = (acc[i][jj * 4 + 1] + b[col + 1]) * scale;
            r4.z = (acc[i][jj * 4 + 2] + b[col + 2]) * scale;
            r4.w = (acc[i][jj * 4 + 3] + b[col + 3]) * scale;
            *(float4*)&O[(size_t)row * DD + col] = r4;
        }
    }
}

// ---------------------------------------------------------------------------
// Flash attention (fp32): BM=64 q-rows per CTA, BN=128 kv-rows per tile.
// 256 threads (ty=tid/16 in [0,16), tx=tid%16).
// S tile 64x128: thread owns rows ty*4+i (i<4), cols j*16+tx (j<8).
// O tile 64x512: thread owns rows ty*4+i, cols c*64+tx*4+j (c<8, j<4).
// Online softmax state (m, l) per row, replicated across the 16 tx lanes.
// ---------------------------------------------------------------------------
// smem layout (floats):
//   Qs [64 k][68]    : k-major chunk of q   (pad 64->68)
//   Ks [64 k][132]   : k-major chunk of k   (pad 128->132)
//   Ps [128 n][68]   : transposed probabilities
//   Vs [64][516]     : v chunk              (pad 512->516)
#define QS_OFF 0
#define KS_OFF (QS_OFF + 64 * 68)
#define PS_OFF (KS_OFF + 64 * 132)
#define VS_OFF (PS_OFF + 128 * 68)
#define SMEM_FLOATS (VS_OFF + 64 * 516)
#define SMEM_BYTES (SMEM_FLOATS * 4)

__global__ __launch_bounds__(256, 1) void attn_kernel(float* __restrict__ out)
{
    extern __shared__ float sm[];
    float* Qs = sm + QS_OFF;
    float* Ks = sm + KS_OFF;
    float* Ps = sm + PS_OFF;
    float* Vs = sm + VS_OFF;

    const int tid = threadIdx.x;
    const int tx = tid & 15, ty = tid >> 4;
    const int rowBase = blockIdx.x * 64;

    float o[4][32];
#pragma unroll
    for (int i = 0; i < 4; ++i)
#pragma unroll
        for (int c = 0; c < 32; ++c) o[i][c] = 0.0f;

    float m_run[4], l_run[4];
#pragma unroll
    for (int i = 0; i < 4; ++i) { m_run[i] = -3.0e38f; l_run[i] = 0.0f; }

    for (int mt = 0; mt < NKV / 128; ++mt) {
        const int nBase = mt * 128;

        float s[4][8];
#pragma unroll
        for (int i = 0; i < 4; ++i)
#pragma unroll
            for (int j = 0; j < 8; ++j) s[i][j] = 0.0f;

        // ---- S = q_tile @ k_tile^T over D=512 in chunks of 64 ----
        for (int kc = 0; kc < 8; ++kc) {
            const int k0 = kc * 64;
#pragma unroll
            for (int it = 0; it < 4; ++it) {          // Qs: 64 rows x 16 f4
                int idx = tid + 256 * it;
                int r = idx >> 4, c4 = idx & 15;
                float4 v = *(const float4*)&g_q[(size_t)(rowBase + r) * DD + k0 + c4 * 4];
                Qs[(c4 * 4 + 0) * 68 + r] = v.x; Qs[(c4 * 4 + 1) * 68 + r] = v.y;
                Qs[(c4 * 4 + 2) * 68 + r] = v.z; Qs[(c4 * 4 + 3) * 68 + r] = v.w;
            }
#pragma unroll
            for (int it = 0; it < 8; ++it) {          // Ks: 128 rows x 16 f4
                int idx = tid + 256 * it;
                int r = idx >> 4, c4 = idx & 15;
                float4 v = *(const float4*)&g_k[(size_t)(nBase + r) * DD + k0 + c4 * 4];
                Ks[(c4 * 4 + 0) * 132 + r] = v.x; Ks[(c4 * 4 + 1) * 132 + r] = v.y;
                Ks[(c4 * 4 + 2) * 132 + r] = v.z; Ks[(c4 * 4 + 3) * 132 + r] = v.w;
            }
            __syncthreads();
#pragma unroll 4
            for (int k = 0; k < 64; ++k) {
                float4 q4 = *(const float4*)&Qs[k * 68 + ty * 4];
                float kr[8];
#pragma unroll
                for (int j = 0; j < 8; ++j) kr[j] = Ks[k * 132 + j * 16 + tx];
#pragma unroll
                for (int j = 0; j < 8; ++j) {
                    s[0][j] += q4.x * kr[j];
                    s[1][j] += q4.y * kr[j];
                    s[2][j] += q4.z * kr[j];
                    s[3][j] += q4.w * kr[j];
                }
            }
            __syncthreads();
        }

        // ---- online softmax (scale already folded into q) ----
        float mx[4], rsum[4];
#pragma unroll
        for (int i = 0; i < 4; ++i) {
            mx[i] = s[i][0];
#pragma unroll
            for (int j = 1; j < 8; ++j) mx[i] = fmaxf(mx[i], s[i][j]);
        }
#pragma unroll
        for (int off = 1; off < 16; off <<= 1)
#pragma unroll
            for (int i = 0; i < 4; ++i)
                mx[i] = fmaxf(mx[i], __shfl_xor_sync(0xffffffffu, mx[i], off));

#pragma unroll
        for (int i = 0; i < 4; ++i) {
            float newm = fmaxf(m_run[i], mx[i]);
            float corr = __expf(m_run[i] - newm);
            m_run[i] = newm;
            rsum[i] = 0.0f;
#pragma unroll
            for (int j = 0; j < 8; ++j) {
                float p = __expf(s[i][j] - newm);
                s[i][j] = p;
                rsum[i] += p;
            }
            l_run[i] *= corr;
#pragma unroll
            for (int c = 0; c < 32; ++c) o[i][c] *= corr;
        }
#pragma unroll
        for (int off = 1; off < 16; off <<= 1)
#pragma unroll
            for (int i = 0; i < 4; ++i)
                rsum[i] += __shfl_xor_sync(0xffffffffu, rsum[i], off);
#pragma unroll
        for (int i = 0; i < 4; ++i) l_run[i] += rsum[i];

        // write P transposed: Ps[n][m]
#pragma unroll
        for (int j = 0; j < 8; ++j)
#pragma unroll
            for (int i = 0; i < 4; ++i)
                Ps[(j * 16 + tx) * 68 + ty * 4 + i] = s[i][j];
        __syncthreads();

        // ---- O += P @ V over the 128 kv rows, in two 64-row halves ----
        for (int h = 0; h < 2; ++h) {
#pragma unroll
            for (int it = 0; it < 32; ++it) {          // Vs: 64 rows x 128 f4
                int idx = tid + 256 * it;
                int r = idx >> 7, c4 = idx & 127;
                float4 v = *(const float4*)&g_v[(size_t)(nBase + h * 64 + r) * DD + c4 * 4];
                *(float4*)&Vs[r * 516 + c4 * 4] = v;
            }
            __syncthreads();
#pragma unroll 4
            for (int nn = 0; nn < 64; ++nn) {
                float4 p4 = *(const float4*)&Ps[(h * 64 + nn) * 68 + ty * 4];
#pragma unroll
                for (int c = 0; c < 8; ++c) {
                    float4 vv = *(const float4*)&Vs[nn * 516 + c * 64 + tx * 4];
                    o[0][c * 4 + 0] += p4.x * vv.x;
                    o[0][c * 4 + 1] += p4.x * vv.y;
                    o[0][c * 4 + 2] += p4.x * vv.z;
                    o[0][c * 4 + 3] += p4.x * vv.w;
                    o[1][c * 4 + 0] += p4.y * vv.x;
                    o[1][c * 4 + 1] += p4.y * vv.y;
                    o[1][c * 4 + 2] += p4.y * vv.z;
                    o[1][c * 4 + 3] += p4.y * vv.w;
                    o[2][c * 4 + 0] += p4.z * vv.x;
                    o[2][c * 4 + 1] += p4.z * vv.y;
                    o[2][c * 4 + 2] += p4.z * vv.z;
                    o[2][c * 4 + 3] += p4.z * vv.w;
                    o[3][c * 4 + 0] += p4.w * vv.x;
                    o[3][c * 4 + 1] += p4.w * vv.y;
                    o[3][c * 4 + 2] += p4.w * vv.z;
                    o[3][c * 4 + 3] += p4.w * vv.w;
                }
            }
            __syncthreads();
        }
    }

    // ---- epilogue: O /= l ----
#pragma unroll
    for (int i = 0; i < 4; ++i) {
        float inv = 1.0f / l_run[i];
        int row = rowBase + ty * 4 + i;
#pragma unroll
        for (int c = 0; c < 8; ++c) {
            float4 r4;
            r4.x = o[i][c * 4 + 0] * inv;
            r4.y = o[i][c * 4 + 1] * inv;
            r4.z = o[i][c * 4 + 2] * inv;
            r4.w = o[i][c * 4 + 3] * inv;
            *(float4*)&out[(size_t)row * DD + c * 64 + tx * 4] = r4;
        }
    }
}

// ---------------------------------------------------------------------------
extern "C" void kernel_launch(void* const* d_in, const int* in_sizes, int n_in,
                              void* d_out, int out_size)
{
    const float* x   = (const float*)d_in[0];
    const float* dom = (const float*)d_in[1];
    const float* Wq  = (const float*)d_in[2];
    const float* bq  = (const float*)d_in[3];
    const float* Wk  = (const float*)d_in[4];
    const float* bk  = (const float*)d_in[5];
    const float* Wv  = (const float*)d_in[6];
    const float* bv  = (const float*)d_in[7];
    float* out = (float*)d_out;

    dim3 gproj(DD / 128, NQ / 128, 3);
    proj_kernel<<<gproj, 256>>>(x, dom, Wq, bq, Wk, bk, Wv, bv);

    cudaFuncSetAttribute(attn_kernel, cudaFuncAttributeMaxDynamicSharedMemorySize,
                         SMEM_BYTES);
    attn_kernel<<<NQ / 64, 256, SMEM_BYTES>>>(out);
}